// round 2
// baseline (speedup 1.0000x reference)
#include <cuda_runtime.h>
#include <mma.h>
#include <math.h>

using namespace nvcuda;

// Problem constants
#define B_DIM   16384
#define I_DIM   512
#define H_DIM   512

// Tiling
#define BM      128          // batch rows per CTA
#define HTILE   32           // h values per CTA
#define BN      128          // gate columns per CTA = 4 gates * HTILE
#define BK      32           // k-chunk
#define LDAB    (BK + 8)     // shared stride for A/B tiles (160B, 16B-multiple)
#define LDC     (BN + 4)     // shared stride for C staging (528B, 16B-multiple)

#define NTHREADS 256

__global__ __launch_bounds__(NTHREADS)
void slstm_fused_kernel(const float* __restrict__ input,
                        const float* __restrict__ h_prev,
                        const float* __restrict__ c_prev,
                        const float* __restrict__ m_prev,
                        const float* __restrict__ n_prev,
                        const float* __restrict__ Wxh,
                        const float* __restrict__ bxh,
                        const float* __restrict__ Whh,
                        const float* __restrict__ bhh,
                        float* __restrict__ out)
{
    extern __shared__ float smem[];
    float* As = smem;                    // [BM][LDAB]
    float* Bs = smem + BM * LDAB;        // [BN][LDAB]

    const int tid  = threadIdx.x;
    const int warp = tid >> 5;
    const int h0   = blockIdx.x * HTILE; // h tile
    const int b0   = blockIdx.y * BM;    // batch tile

    // 8 warps: 4 along M (32 rows each), 2 along N (64 cols each)
    const int wm = warp & 3;
    const int wn = warp >> 2;

    wmma::fragment<wmma::accumulator, 16, 16, 8, float> c_frag[2][4];
    #pragma unroll
    for (int i = 0; i < 2; i++)
        #pragma unroll
        for (int j = 0; j < 4; j++)
            wmma::fill_fragment(c_frag[i][j], 0.0f);

    // K loop over concatenated [input | h_prev] (K = 1024)
    for (int kk = 0; kk < I_DIM + H_DIM; kk += BK) {
        const float* Asrc = (kk < I_DIM) ? input : h_prev;
        const float* Wsrc = (kk < I_DIM) ? Wxh   : Whh;
        const int kb = kk & (I_DIM - 1);  // kk mod 512

        // Load A tile: BM x BK floats (float4 vectorized)
        #pragma unroll
        for (int i = 0; i < (BM * BK / 4) / NTHREADS; i++) {
            int idx = tid + i * NTHREADS;        // float4 index
            int r  = idx >> 3;                   // BK/4 = 8 float4 per row
            int c4 = idx & 7;
            float4 v = *reinterpret_cast<const float4*>(
                Asrc + (size_t)(b0 + r) * I_DIM + kb + c4 * 4);
            float* dst = As + r * LDAB + c4 * 4;
            dst[0] = v.x; dst[1] = v.y; dst[2] = v.z; dst[3] = v.w;
        }
        // Load B tile: BN x BK floats. Local row c -> gate g = c>>5, hh = c&31,
        // global weight row j = g*512 + h0 + hh.
        #pragma unroll
        for (int i = 0; i < (BN * BK / 4) / NTHREADS; i++) {
            int idx = tid + i * NTHREADS;
            int r  = idx >> 3;
            int c4 = idx & 7;
            int g  = r >> 5;
            int hh = r & 31;
            int j  = g * H_DIM + h0 + hh;
            float4 v = *reinterpret_cast<const float4*>(
                Wsrc + (size_t)j * I_DIM + kb + c4 * 4);
            float* dst = Bs + r * LDAB + c4 * 4;
            dst[0] = v.x; dst[1] = v.y; dst[2] = v.z; dst[3] = v.w;
        }
        __syncthreads();

        #pragma unroll
        for (int ks = 0; ks < BK; ks += 8) {
            wmma::fragment<wmma::matrix_a, 16, 16, 8, wmma::precision::tf32, wmma::row_major> a_frag[2];
            wmma::fragment<wmma::matrix_b, 16, 16, 8, wmma::precision::tf32, wmma::col_major> b_frag[4];
            #pragma unroll
            for (int i = 0; i < 2; i++) {
                wmma::load_matrix_sync(a_frag[i], As + (wm * 32 + i * 16) * LDAB + ks, LDAB);
                #pragma unroll
                for (int t = 0; t < a_frag[i].num_elements; t++)
                    a_frag[i].x[t] = wmma::__float_to_tf32(a_frag[i].x[t]);
            }
            #pragma unroll
            for (int j = 0; j < 4; j++) {
                wmma::load_matrix_sync(b_frag[j], Bs + (wn * 64 + j * 16) * LDAB + ks, LDAB);
                #pragma unroll
                for (int t = 0; t < b_frag[j].num_elements; t++)
                    b_frag[j].x[t] = wmma::__float_to_tf32(b_frag[j].x[t]);
            }
            #pragma unroll
            for (int i = 0; i < 2; i++)
                #pragma unroll
                for (int j = 0; j < 4; j++)
                    wmma::mma_sync(c_frag[i][j], a_frag[i], b_frag[j], c_frag[i][j]);
        }
        __syncthreads();
    }

    // Stage C through shared (reuse smem): Cs[BM][LDC]
    float* Cs = smem;
    #pragma unroll
    for (int i = 0; i < 2; i++)
        #pragma unroll
        for (int j = 0; j < 4; j++)
            wmma::store_matrix_sync(Cs + (wm * 32 + i * 16) * LDC + wn * 64 + j * 16,
                                    c_frag[i][j], LDC, wmma::mem_row_major);
    __syncthreads();

    // Elementwise epilogue: each thread handles 16 (b, h) elements
    const size_t BH = (size_t)B_DIM * H_DIM;
    #pragma unroll
    for (int p = 0; p < (BM * HTILE) / NTHREADS; p++) {
        int lin = tid + p * NTHREADS;
        int bl  = lin >> 5;          // local batch row
        int hh  = lin & 31;          // local h
        int b   = b0 + bl;
        int h   = h0 + hh;

        // gate order from jnp.split: i, f, z, o
        float ig = Cs[bl * LDC +  0 + hh] + bxh[0 * H_DIM + h] + bhh[0 * H_DIM + h];
        float fg = Cs[bl * LDC + 32 + hh] + bxh[1 * H_DIM + h] + bhh[1 * H_DIM + h];
        float zg = Cs[bl * LDC + 64 + hh] + bxh[2 * H_DIM + h] + bhh[2 * H_DIM + h];
        float og = Cs[bl * LDC + 96 + hh] + bxh[3 * H_DIM + h] + bhh[3 * H_DIM + h];

        size_t idx = (size_t)b * H_DIM + h;
        float mp = m_prev[idx];
        float cp = c_prev[idx];
        float np = n_prev[idx];

        float z_t = tanhf(zg);
        float o_t = 1.0f / (1.0f + expf(-og));
        float m_t = fmaxf(fg + mp, ig);
        float i_t = expf(ig - m_t);
        float f_t = expf(fg + mp - m_t);
        float c_t = f_t * cp + i_t * z_t;
        float n_t = f_t * np + i_t;
        float h_t = o_t * (c_t / n_t);

        out[0 * BH + idx] = h_t;
        out[1 * BH + idx] = c_t;
        out[2 * BH + idx] = m_t;
        out[3 * BH + idx] = n_t;
    }
}

extern "C" void kernel_launch(void* const* d_in, const int* in_sizes, int n_in,
                              void* d_out, int out_size)
{
    const float* input  = (const float*)d_in[0];
    const float* h_prev = (const float*)d_in[1];
    const float* c_prev = (const float*)d_in[2];
    const float* m_prev = (const float*)d_in[3];
    const float* n_prev = (const float*)d_in[4];
    const float* Wxh    = (const float*)d_in[5];
    const float* bxh    = (const float*)d_in[6];
    const float* Whh    = (const float*)d_in[7];
    const float* bhh    = (const float*)d_in[8];
    float* out = (float*)d_out;

    // Shared memory: max(A+B tiles, C staging)
    int smem_ab = 2 * BM * LDAB * (int)sizeof(float);   // 40960
    int smem_c  = BM * LDC * (int)sizeof(float);        // 67584
    int smem = smem_ab > smem_c ? smem_ab : smem_c;

    cudaFuncSetAttribute(slstm_fused_kernel,
                         cudaFuncAttributeMaxDynamicSharedMemorySize, smem);

    dim3 grid(H_DIM / HTILE, B_DIM / BM);   // (16, 128)
    dim3 block(NTHREADS);
    slstm_fused_kernel<<<grid, block, smem>>>(
        input, h_prev, c_prev, m_prev, n_prev, Wxh, bxh, Whh, bhh, out);
}

// round 4
// speedup vs baseline: 3.4734x; 3.4734x over previous
#include <cuda_runtime.h>
#include <cuda.h>
#include <cstdint>

// ---------------- problem/tiling constants ----------------
#define B_DIM    16384
#define H_DIM    512
#define BM       128        // batch rows per CTA (M)
#define BN       256        // gate cols per CTA = 4 gates * 64 h (N)
#define BK       32         // K floats per stage (128 bytes = SW128 atom)
#define NSTAGE   4
#define NKSTEP   32         // 1024 / BK
#define NTHREADS 512        // 16 warps: 4 along M x 4 along N

// ---------------- smem layout (bytes) ----------------
#define OFF_FULL   0                        // 4 x 8B mbarriers (TMA full)
#define OFF_BIAS   128                      // 256 floats
#define OFF_DATA   2048                     // 1024-aligned tile data
#define A_BYTES    (BM * 128)               // 16384
#define B_BYTES    (BN * 128)               // 32768
#define STAGE_BYTES (A_BYTES + B_BYTES)     // 49152
#define A_OFF(s)   (OFF_DATA + (s) * STAGE_BYTES)
#define B_OFF(s)   (A_OFF(s) + A_BYTES)
#define SMEM_TOTAL (OFF_DATA + NSTAGE * STAGE_BYTES)   // 198656
#define DST_LD     268                      // epilogue staging stride (floats)

// ---------------- PTX helpers ----------------
__device__ __forceinline__ uint32_t smem_u32(const void* p) {
    uint32_t a;
    asm("{ .reg .u64 t; cvta.to.shared.u64 t, %1; cvt.u32.u64 %0, t; }" : "=r"(a) : "l"(p));
    return a;
}

#define MBARRIER_INIT(addr, cnt) \
    asm volatile("mbarrier.init.shared.b64 [%0], %1;" :: "r"(addr), "r"((uint32_t)(cnt)) : "memory")

#define MBARRIER_EXPECT_TX(addr, bytes) \
    asm volatile("mbarrier.arrive.expect_tx.shared.b64 _, [%0], %1;" :: "r"(addr), "r"((uint32_t)(bytes)) : "memory")

#define MBARRIER_WAIT_PARITY(addr, parity) do {                                   \
    asm volatile(                                                                 \
        "{\n\t.reg .pred P;\n\t"                                                  \
        "WL_%=:\n\t"                                                              \
        "mbarrier.try_wait.parity.acquire.cta.shared::cta.b64 P, [%0], %1, 0x989680;\n\t" \
        "@P bra.uni WD_%=;\n\t"                                                   \
        "bra.uni WL_%=;\n\t"                                                      \
        "WD_%=:\n\t}"                                                             \
        :: "r"(addr), "r"((uint32_t)(parity)) : "memory");                        \
} while (0)

#define TMA_LOAD_2D(dst, map, c0, c1, mbar)                                        \
    asm volatile(                                                                  \
        "cp.async.bulk.tensor.2d.shared::cta.global.tile.mbarrier::complete_tx::bytes " \
        "[%0], [%1, {%2, %3}], [%4];"                                              \
        :: "r"((uint32_t)(dst)), "l"(map), "r"((int32_t)(c0)), "r"((int32_t)(c1)), \
           "r"((uint32_t)(mbar)) : "memory")

__device__ __forceinline__ uint32_t lds32(uint32_t addr) {
    uint32_t v;
    asm volatile("ld.shared.b32 %0, [%1];" : "=r"(v) : "r"(addr));
    return v;
}

__device__ __forceinline__ void mma_tf32(float* d, const uint32_t* a, const uint32_t* b) {
    asm volatile(
        "mma.sync.aligned.m16n8k8.row.col.f32.tf32.tf32.f32 "
        "{%0,%1,%2,%3}, {%4,%5,%6,%7}, {%8,%9}, {%0,%1,%2,%3};"
        : "+f"(d[0]), "+f"(d[1]), "+f"(d[2]), "+f"(d[3])
        : "r"(a[0]), "r"(a[1]), "r"(a[2]), "r"(a[3]), "r"(b[0]), "r"(b[1]));
}

__device__ __forceinline__ float tanh_ap(float x) {
    float y; asm("tanh.approx.f32 %0, %1;" : "=f"(y) : "f"(x)); return y;
}

// ---------------- TMA stage issue ----------------
__device__ __forceinline__ void issue_stage(uint32_t sb, int ks, int slot, int b0, int h0,
                                            const CUtensorMap* tmx, const CUtensorMap* tmh,
                                            const CUtensorMap* tmwx, const CUtensorMap* tmwh) {
    uint32_t fb = sb + OFF_FULL + 8 * slot;
    MBARRIER_EXPECT_TX(fb, STAGE_BYTES);
    int kk = ks * BK;
    const CUtensorMap* am = tmx;
    const CUtensorMap* wm = tmwx;
    int kb = kk;
    if (kk >= 512) { am = tmh; wm = tmwh; kb = kk - 512; }
    TMA_LOAD_2D(sb + A_OFF(slot), am, kb, b0, fb);
#pragma unroll
    for (int g = 0; g < 4; g++)
        TMA_LOAD_2D(sb + B_OFF(slot) + g * 8192, wm, kb, g * H_DIM + h0, fb);
}

// ---------------- kernel ----------------
__global__ __launch_bounds__(NTHREADS, 1)
void slstm_mma(const __grid_constant__ CUtensorMap tmx,
               const __grid_constant__ CUtensorMap tmh,
               const __grid_constant__ CUtensorMap tmwx,
               const __grid_constant__ CUtensorMap tmwh,
               const float* __restrict__ c_prev,
               const float* __restrict__ m_prev,
               const float* __restrict__ n_prev,
               const float* __restrict__ bxh,
               const float* __restrict__ bhh,
               float* __restrict__ out)
{
    extern __shared__ __align__(1024) char smem[];
    const uint32_t sb = smem_u32(smem);
    const int tid  = threadIdx.x;
    const int warp = tid >> 5;
    const int lane = tid & 31;
    const int wm = warp & 3;          // M group (32 rows each)
    const int wn = warp >> 2;         // N group (64 cols each) == gate index
    const int g  = lane >> 2;         // octet row within fragment
    const int h0 = blockIdx.x * 64;
    const int b0 = blockIdx.y * BM;

    if (tid == 0) {
#pragma unroll
        for (int i = 0; i < NSTAGE; i++)
            MBARRIER_INIT(sb + OFF_FULL + 8 * i, 1);
    }
    if (tid < 256) {
        int j = (tid >> 6) * H_DIM + h0 + (tid & 63);
        ((float*)(smem + OFF_BIAS))[tid] = bxh[j] + bhh[j];
    }
    __syncthreads();

    if (tid == 0) {
#pragma unroll
        for (int s = 0; s < NSTAGE; s++)
            issue_stage(sb, s, s, b0, h0, &tmx, &tmh, &tmwx, &tmwh);
    }

    // swizzle XOR constant: all rows this thread touches are == g (mod 8)
    const uint32_t X   = (uint32_t)g << 4;           // (row&7)*16
    const uint32_t c0b = (uint32_t)(lane & 3) << 2;  // k-col byte offset (bits 2-3)

    float acc[2][8][4];
#pragma unroll
    for (int mi = 0; mi < 2; mi++)
#pragma unroll
        for (int j = 0; j < 8; j++)
#pragma unroll
            for (int e = 0; e < 4; e++) acc[mi][j][e] = 0.0f;

    for (int s = 0; s < NKSTEP; s++) {
        const int slot = s & 3;
        MBARRIER_WAIT_PARITY(sb + OFF_FULL + 8 * slot, (s >> 2) & 1);

        const uint32_t Abase = sb + A_OFF(slot) + (uint32_t)(wm * 32 + g) * 128 + c0b;
        const uint32_t Bbase = sb + B_OFF(slot) + (uint32_t)wn * 8192 + (uint32_t)g * 128 + c0b;

#pragma unroll
        for (int k8 = 0; k8 < 4; k8++) {
            const uint32_t o0 = ((uint32_t)(k8 * 32)) ^ X;        // cols k..k+3
            const uint32_t o1 = ((uint32_t)(k8 * 32 + 16)) ^ X;   // cols k+4..k+7

            uint32_t a[2][4];
#pragma unroll
            for (int mi = 0; mi < 2; mi++) {
                uint32_t ab = Abase + (uint32_t)mi * 2048;
                a[mi][0] = lds32(ab + o0);           // row g
                a[mi][1] = lds32(ab + 1024 + o0);    // row g+8
                a[mi][2] = lds32(ab + o1);
                a[mi][3] = lds32(ab + 1024 + o1);
            }
            uint32_t b[8][2];
#pragma unroll
            for (int j = 0; j < 8; j++) {
                uint32_t bb = Bbase + (uint32_t)j * 1024;
                b[j][0] = lds32(bb + o0);
                b[j][1] = lds32(bb + o1);
            }
#pragma unroll
            for (int mi = 0; mi < 2; mi++)
#pragma unroll
                for (int j = 0; j < 8; j++)
                    mma_tf32(acc[mi][j], a[mi], b[j]);
        }

        __syncthreads();   // all warps done reading this slot
        if (tid == 0 && s + NSTAGE < NKSTEP)
            issue_stage(sb, s + NSTAGE, slot, b0, h0, &tmx, &tmh, &tmwx, &tmwh);
    }

    // ---- stage accumulators to smem: Dst[128][DST_LD] ----
    float* Dst = (float*)(smem + OFF_DATA);
    {
        const int r0 = wm * 32 + g;
        const int cb = wn * 64 + 2 * (lane & 3);
#pragma unroll
        for (int mi = 0; mi < 2; mi++)
#pragma unroll
            for (int j = 0; j < 8; j++) {
                int r = r0 + mi * 16;
                int c = cb + j * 8;
                *(float2*)(Dst + (size_t)r * DST_LD + c) =
                    make_float2(acc[mi][j][0], acc[mi][j][1]);
                *(float2*)(Dst + (size_t)(r + 8) * DST_LD + c) =
                    make_float2(acc[mi][j][2], acc[mi][j][3]);
            }
    }
    __syncthreads();

    // ---- fused elementwise epilogue: coalesced ----
    const float* bias = (const float*)(smem + OFF_BIAS);
    const size_t BH = (size_t)B_DIM * H_DIM;
#pragma unroll 4
    for (int e = 0; e < (BM * 64) / NTHREADS; e++) {
        int idx = tid + e * NTHREADS;
        int r = idx >> 6, hh = idx & 63;
        const float* drow = Dst + (size_t)r * DST_LD;
        float ig = drow[hh]       + bias[hh];
        float fg = drow[64 + hh]  + bias[64 + hh];
        float zg = drow[128 + hh] + bias[128 + hh];
        float og = drow[192 + hh] + bias[192 + hh];

        size_t gi = (size_t)(b0 + r) * H_DIM + h0 + hh;
        float cp = c_prev[gi], mp = m_prev[gi], np = n_prev[gi];

        float zt = tanh_ap(zg);
        float ot = 0.5f * tanh_ap(0.5f * og) + 0.5f;   // sigmoid
        float aa = fg + mp;
        float mt = fmaxf(aa, ig);
        float em = __expf(0.0f - fabsf(aa - ig));      // single exp
        float ft = (aa >= ig) ? 1.0f : em;
        float it = (aa >= ig) ? em : 1.0f;
        float ct = ft * cp + it * zt;
        float nt = ft * np + it;
        float ht = ot * __fdividef(ct, nt);

        out[gi]          = ht;
        out[BH + gi]     = ct;
        out[2 * BH + gi] = mt;
        out[3 * BH + gi] = nt;
    }
}

// ---------------- host side ----------------
typedef CUresult (*PFN_encodeTiled)(CUtensorMap*, CUtensorMapDataType, cuuint32_t, void*,
                                    const cuuint64_t*, const cuuint64_t*, const cuuint32_t*,
                                    const cuuint32_t*, CUtensorMapInterleave, CUtensorMapSwizzle,
                                    CUtensorMapL2promotion, CUtensorMapFloatOOBfill);

static PFN_encodeTiled get_encoder() {
    static PFN_encodeTiled fn = nullptr;
    if (!fn) {
        void* p = nullptr;
        cudaDriverEntryPointQueryResult st;
#if CUDART_VERSION >= 12050
        cudaGetDriverEntryPointByVersion("cuTensorMapEncodeTiled", &p, 12000, cudaEnableDefault, &st);
#else
        cudaGetDriverEntryPoint("cuTensorMapEncodeTiled", &p, cudaEnableDefault, &st);
#endif
        fn = (PFN_encodeTiled)p;
    }
    return fn;
}

static void make_map(CUtensorMap* m, const void* ptr, uint64_t d0, uint64_t d1,
                     uint32_t box0, uint32_t box1) {
    cuuint64_t dims[2]    = {d0, d1};
    cuuint64_t strides[1] = {d0 * 4};
    cuuint32_t box[2]     = {box0, box1};
    cuuint32_t es[2]      = {1, 1};
    get_encoder()(m, CU_TENSOR_MAP_DATA_TYPE_FLOAT32, 2, (void*)ptr, dims, strides, box, es,
                  CU_TENSOR_MAP_INTERLEAVE_NONE, CU_TENSOR_MAP_SWIZZLE_128B,
                  CU_TENSOR_MAP_L2_PROMOTION_L2_128B, CU_TENSOR_MAP_FLOAT_OOB_FILL_NONE);
}

extern "C" void kernel_launch(void* const* d_in, const int* in_sizes, int n_in,
                              void* d_out, int out_size)
{
    const float* input  = (const float*)d_in[0];
    const float* h_prev = (const float*)d_in[1];
    const float* c_prev = (const float*)d_in[2];
    const float* m_prev = (const float*)d_in[3];
    const float* n_prev = (const float*)d_in[4];
    const float* Wxh    = (const float*)d_in[5];
    const float* bxh    = (const float*)d_in[6];
    const float* Whh    = (const float*)d_in[7];
    const float* bhh    = (const float*)d_in[8];
    float* out = (float*)d_out;

    CUtensorMap tmx, tmh, tmwx, tmwh;
    make_map(&tmx,  input,  512, (uint64_t)B_DIM, BK, BM);       // A: input
    make_map(&tmh,  h_prev, 512, (uint64_t)B_DIM, BK, BM);       // A: h_prev
    make_map(&tmwx, Wxh,    512, 4 * (uint64_t)H_DIM, BK, 64);   // B: Wxh (per-gate box)
    make_map(&tmwh, Whh,    512, 4 * (uint64_t)H_DIM, BK, 64);   // B: Whh

    cudaFuncSetAttribute(slstm_mma, cudaFuncAttributeMaxDynamicSharedMemorySize, SMEM_TOTAL);

    dim3 grid(H_DIM / 64, B_DIM / BM);  // (8, 128)
    slstm_mma<<<grid, NTHREADS, SMEM_TOTAL>>>(tmx, tmh, tmwx, tmwh,
                                              c_prev, m_prev, n_prev, bxh, bhh, out);
}